// round 15
// baseline (speedup 1.0000x reference)
#include <cuda_runtime.h>
#include <cuda_bf16.h>
#include <cstdint>
#include <cstddef>

// Problem constants
constexpr int BATCH = 256;
constexpr int SEQ   = 512;
constexpr int INP   = 128;
constexpr int HID   = 256;
constexpr int G4H   = 1024;   // 4*HID

// Persistent recurrent kernel config
constexpr int GRID_P    = 128;   // 8 row-blocks x 16 unit-blocks
constexpr int THREADS_R = 256;   // 8 warps
constexpr int GROUP_CTAS = 16;   // CTAs per row-block sync group (== cluster size)

// ---------------- scratch ----------------
__device__ float g_xpre0[(size_t)BATCH * SEQ * G4H];       // 512 MB
__device__ float g_xpre1[(size_t)BATCH * SEQ * G4H];       // 512 MB
__device__ __nv_bfloat16 g_hbf[2][2][BATCH * HID];         // [buf][hi/lo][B*H]
__device__ unsigned int g_grp_count[8][64];
__device__ unsigned int g_grp_gen[8][64];

__device__ __forceinline__ uint32_t smem_u32(const void* p) {
    uint32_t a;
    asm("{ .reg .u64 t; cvta.to.shared.u64 t, %1; cvt.u32.u64 %0, t; }" : "=r"(a) : "l"(p));
    return a;
}

// ================= mma.sync helpers =================
__device__ __forceinline__ void ldmx4(uint32_t* r, uint32_t addr) {
    asm volatile("ldmatrix.sync.aligned.m8n8.x4.shared.b16 {%0,%1,%2,%3}, [%4];"
                 : "=r"(r[0]), "=r"(r[1]), "=r"(r[2]), "=r"(r[3]) : "r"(addr));
}
__device__ __forceinline__ void mma16816(float* d, const uint32_t* a,
                                         uint32_t b0, uint32_t b1) {
    asm volatile(
        "mma.sync.aligned.m16n8k16.row.col.f32.bf16.bf16.f32 "
        "{%0,%1,%2,%3}, {%4,%5,%6,%7}, {%8,%9}, {%0,%1,%2,%3};"
        : "+f"(d[0]), "+f"(d[1]), "+f"(d[2]), "+f"(d[3])
        : "r"(a[0]), "r"(a[1]), "r"(a[2]), "r"(a[3]), "r"(b0), "r"(b1));
}

__device__ __forceinline__ void cvt_pair8(const float* v, uint4& hi, uint4& lo) {
    unsigned hs[8], ls[8];
    #pragma unroll
    for (int j = 0; j < 8; ++j) {
        __nv_bfloat16 h = __float2bfloat16(v[j]);
        float hf = __bfloat162float(h);
        __nv_bfloat16 l = __float2bfloat16(v[j] - hf);
        hs[j] = (unsigned)__bfloat16_as_ushort(h);
        ls[j] = (unsigned)__bfloat16_as_ushort(l);
    }
    hi.x = hs[0] | (hs[1] << 16); hi.y = hs[2] | (hs[3] << 16);
    hi.z = hs[4] | (hs[5] << 16); hi.w = hs[6] | (hs[7] << 16);
    lo.x = ls[0] | (ls[1] << 16); lo.y = ls[2] | (ls[3] << 16);
    lo.z = ls[4] | (ls[5] << 16); lo.w = ls[6] | (ls[7] << 16);
}
__device__ __forceinline__ void cvt_pair4(float4 v, uint2& hi, uint2& lo) {
    float f[4] = {v.x, v.y, v.z, v.w};
    unsigned hs[4], ls[4];
    #pragma unroll
    for (int j = 0; j < 4; ++j) {
        __nv_bfloat16 h = __float2bfloat16(f[j]);
        float hf = __bfloat162float(h);
        __nv_bfloat16 l = __float2bfloat16(f[j] - hf);
        hs[j] = (unsigned)__bfloat16_as_ushort(h);
        ls[j] = (unsigned)__bfloat16_as_ushort(l);
    }
    hi.x = hs[0] | (hs[1] << 16); hi.y = hs[2] | (hs[3] << 16);
    lo.x = ls[0] | (ls[1] << 16); lo.y = ls[2] | (ls[3] << 16);
}

// ================= input-projection GEMM on HMMA (layer 0, validated) =================
constexpr int GM_THREADS = 256;
constexpr int PITCH = 80;
constexpr int PLANE = 128 * PITCH;
constexpr int SB_BIAS = 0;
constexpr int SB_AH = 1024;
constexpr int SB_AL = SB_AH + PLANE;
constexpr int SB_BH = SB_AL + PLANE;
constexpr int SB_BL = SB_BH + PLANE;
constexpr size_t GM_SMEM = SB_BL + PLANE;

template<int K>
__global__ void __launch_bounds__(GM_THREADS)
gemm_mma(const float* __restrict__ A, const float* __restrict__ W,
         const float* __restrict__ b1, const float* __restrict__ b2,
         float* __restrict__ Cout)
{
    extern __shared__ char sm[];
    const uint32_t sbase = smem_u32(sm);
    float* sbias = (float*)(sm + SB_BIAS);

    const int tid  = threadIdx.x;
    const int lane = tid & 31;
    const int warp = tid >> 5;
    const int wm   = warp >> 2;
    const int wn   = warp & 3;
    const int n0   = blockIdx.x * 128;
    const size_t m0 = (size_t)blockIdx.y * 128;

    if (tid < 128) sbias[tid] = b1[n0 + tid] + b2[n0 + tid];

    const int lrow  = tid >> 1;
    const int lhalf = tid & 1;
    const float* gA = A + (m0 + lrow) * K + lhalf * 16;
    const float* gB = W + (size_t)(n0 + lrow) * K + lhalf * 16;

    float acc[4][4][4] = {};
    float ra[16], rb[16];

    #pragma unroll
    for (int q = 0; q < 4; ++q) {
        *(float4*)(ra + q * 4) = *(const float4*)(gA + q * 4);
        *(float4*)(rb + q * 4) = *(const float4*)(gB + q * 4);
    }

    constexpr int NC = K / 32;
    for (int c = 0; c < NC; ++c) {
        #pragma unroll
        for (int j = 0; j < 2; ++j) {
            uint4 hi, lo;
            uint32_t off = (uint32_t)(lrow * PITCH + lhalf * 32 + j * 16);
            cvt_pair8(ra + j * 8, hi, lo);
            *(uint4*)(sm + SB_AH + off) = hi;
            *(uint4*)(sm + SB_AL + off) = lo;
            cvt_pair8(rb + j * 8, hi, lo);
            *(uint4*)(sm + SB_BH + off) = hi;
            *(uint4*)(sm + SB_BL + off) = lo;
        }
        __syncthreads();

        if (c + 1 < NC) {
            #pragma unroll
            for (int q = 0; q < 4; ++q) {
                *(float4*)(ra + q * 4) = *(const float4*)(gA + (c + 1) * 32 + q * 4);
                *(float4*)(rb + q * 4) = *(const float4*)(gB + (c + 1) * 32 + q * 4);
            }
        }

        #pragma unroll
        for (int kb = 0; kb < 2; ++kb) {
            uint32_t Ah[4][4], Al[4][4], Bh[2][4], Bl[2][4];
            const uint32_t acol = (uint32_t)(kb * 32 + (lane >> 4) * 16);
            #pragma unroll
            for (int mi = 0; mi < 4; ++mi) {
                uint32_t rowoff = (uint32_t)((wm * 64 + mi * 16 + (lane & 15)) * PITCH) + acol;
                ldmx4(Ah[mi], sbase + SB_AH + rowoff);
                ldmx4(Al[mi], sbase + SB_AL + rowoff);
            }
            const uint32_t bcol = (uint32_t)(kb * 32 + ((lane >> 3) & 1) * 16);
            #pragma unroll
            for (int nb = 0; nb < 2; ++nb) {
                uint32_t rowoff = (uint32_t)((wn * 32 + nb * 16 + (lane & 7) + ((lane >> 4) << 3)) * PITCH) + bcol;
                ldmx4(Bh[nb], sbase + SB_BH + rowoff);
                ldmx4(Bl[nb], sbase + SB_BL + rowoff);
            }
            #pragma unroll
            for (int mi = 0; mi < 4; ++mi) {
                #pragma unroll
                for (int ni = 0; ni < 4; ++ni) {
                    const int nb = ni >> 1, h = (ni & 1) * 2;
                    mma16816(acc[mi][ni], Ah[mi], Bh[nb][h], Bh[nb][h + 1]);
                    mma16816(acc[mi][ni], Ah[mi], Bl[nb][h], Bl[nb][h + 1]);
                    mma16816(acc[mi][ni], Al[mi], Bh[nb][h], Bh[nb][h + 1]);
                }
            }
        }
        __syncthreads();
    }

    const int g   = lane >> 2;
    const int tig = lane & 3;
    #pragma unroll
    for (int mi = 0; mi < 4; ++mi) {
        const size_t row = m0 + wm * 64 + mi * 16 + g;
        float* dst0 = Cout + row * G4H + n0;
        float* dst8 = dst0 + (size_t)8 * G4H;
        #pragma unroll
        for (int ni = 0; ni < 4; ++ni) {
            const int col = wn * 32 + ni * 8 + tig * 2;
            const float bb0 = sbias[col], bb1 = sbias[col + 1];
            float2 v0 = {acc[mi][ni][0] + bb0, acc[mi][ni][1] + bb1};
            float2 v1 = {acc[mi][ni][2] + bb0, acc[mi][ni][3] + bb1};
            *(float2*)(dst0 + col) = v0;
            *(float2*)(dst8 + col) = v1;
        }
    }
}

// ================= barriers =================
__device__ __forceinline__ void group_sync_atomic(int grp)
{
    __syncthreads();
    if (threadIdx.x == 0) {
        __threadfence();
        unsigned int gen  = *((volatile unsigned int*)&g_grp_gen[grp][0]);
        unsigned int prev = atomicAdd(&g_grp_count[grp][0], 1u);
        if (prev == GROUP_CTAS - 1) {
            g_grp_count[grp][0] = 0;
            __threadfence();
            atomicAdd(&g_grp_gen[grp][0], 1u);
        } else {
            while (*((volatile unsigned int*)&g_grp_gen[grp][0]) == gen) { }
            __threadfence();
        }
    }
    __syncthreads();
}

template<bool CLUSTERED>
__device__ __forceinline__ void step_sync(int grp)
{
    if (CLUSTERED) {
        asm volatile("barrier.cluster.arrive.aligned;" ::: "memory");
        asm volatile("barrier.cluster.wait.aligned;"   ::: "memory");
    } else {
        group_sync_atomic(grp);
    }
}

__device__ __forceinline__ float sigmoidf_(float x) { return 1.0f / (1.0f + __expf(-x)); }

// ================= persistent LSTM recurrence, warp-specialized ========
constexpr int RPITCH  = 528;
constexpr int R_WH_HI = 0;
constexpr int R_WH_LO = R_WH_HI + 64 * RPITCH;
constexpr int R_WN_HI = R_WH_LO + 64 * RPITCH;
constexpr int R_WN_LO = R_WN_HI + 64 * RPITCH;
constexpr int R_AH    = R_WN_LO + 64 * RPITCH;
constexpr int R_AL    = R_AH + 32 * RPITCH;
constexpr int R_GS    = R_AL + 32 * RPITCH;
constexpr int GS_PLANE = 32 * 66;
constexpr int R_CS    = R_GS + 2 * GS_PLANE * 4;
constexpr int R_BN    = R_CS + 32 * 17 * 4;
constexpr size_t R_SMEM = (size_t)R_BN + 64 * 4;    // 188288 B

__device__ __forceinline__ void load_h_tile(char* smr, const __nv_bfloat16* hhi,
                                            const __nv_bfloat16* hlo, int r0, int tid)
{
    #pragma unroll
    for (int it = 0; it < 4; ++it) {
        int idx = tid + it * THREADS_R;
        int row = idx >> 5, ch = idx & 31;
        uint4 v = __ldcg((const uint4*)(hhi + (r0 + row) * HID) + ch);
        *(uint4*)(smr + R_AH + row * RPITCH + ch * 16) = v;
        v = __ldcg((const uint4*)(hlo + (r0 + row) * HID) + ch);
        *(uint4*)(smr + R_AL + row * RPITCH + ch * 16) = v;
    }
}

__device__ __forceinline__ void pair_mma(const uint32_t sbase, int lane, int g4,
                                         int kb0, int kb1, int whi, int wlo,
                                         float acc[2][2][4])
{
    for (int kb = kb0; kb < kb1; ++kb) {
        uint32_t Ahf[2][4], Alf[2][4], Bhf[4], Blf[4];
        const uint32_t acol = (uint32_t)(kb * 32 + (lane >> 4) * 16);
        #pragma unroll
        for (int mi = 0; mi < 2; ++mi) {
            uint32_t ro = (uint32_t)((mi * 16 + (lane & 15)) * RPITCH) + acol;
            ldmx4(Ahf[mi], sbase + R_AH + ro);
            ldmx4(Alf[mi], sbase + R_AL + ro);
        }
        const uint32_t brow = (uint32_t)(g4 * 16 + (lane & 7) + ((lane >> 4) << 3));
        const uint32_t bcol = (uint32_t)(kb * 32 + ((lane >> 3) & 1) * 16);
        ldmx4(Bhf, sbase + whi + brow * RPITCH + bcol);
        ldmx4(Blf, sbase + wlo + brow * RPITCH + bcol);
        #pragma unroll
        for (int mi = 0; mi < 2; ++mi)
            #pragma unroll
            for (int ni = 0; ni < 2; ++ni) {
                const int h2 = ni * 2;
                mma16816(acc[mi][ni], Ahf[mi], Bhf[h2], Bhf[h2 + 1]);
                mma16816(acc[mi][ni], Ahf[mi], Blf[h2], Blf[h2 + 1]);
                mma16816(acc[mi][ni], Alf[mi], Bhf[h2], Bhf[h2 + 1]);
            }
    }
}

__device__ __forceinline__ void proj_store(float* __restrict__ xpre_out, const float* sbn,
                                           float acc2[2][2][4], int t_store,
                                           int r0, int u0, int g4, int gq, int tig)
{
    #pragma unroll
    for (int mi = 0; mi < 2; ++mi) {
        const int row = r0 + mi * 16 + gq;
        float* d0 = xpre_out + ((size_t)row * SEQ + t_store) * G4H + g4 * HID + u0;
        float* d8 = xpre_out + ((size_t)(row + 8) * SEQ + t_store) * G4H + g4 * HID + u0;
        #pragma unroll
        for (int ni = 0; ni < 2; ++ni) {
            const int uu = ni * 8 + tig * 2;
            const float b0 = sbn[g4 * 16 + uu], b1v = sbn[g4 * 16 + uu + 1];
            float2 v0 = {acc2[mi][ni][0] + b0, acc2[mi][ni][1] + b1v};
            float2 v1 = {acc2[mi][ni][2] + b0, acc2[mi][ni][3] + b1v};
            *(float2*)(d0 + uu) = v0;
            *(float2*)(d8 + uu) = v1;
        }
    }
}

template<bool FUSED, bool CLUSTERED>
__global__ void __launch_bounds__(THREADS_R, 1)
lstm_layer_kernel(const float* __restrict__ Whh,
                  const float* __restrict__ xpre_in,
                  const float* __restrict__ Wih_next,
                  const float* __restrict__ bn1,
                  const float* __restrict__ bn2,
                  float* __restrict__ xpre_out,
                  float* __restrict__ y_out,
                  float* __restrict__ out_h,
                  float* __restrict__ out_c)
{
    extern __shared__ char smr[];
    const uint32_t sbase = smem_u32(smr);
    float* Gs0 = (float*)(smr + R_GS);
    float* Gs1 = Gs0 + GS_PLANE;
    float* Cs  = (float*)(smr + R_CS);
    float* sbn = (float*)(smr + R_BN);

    const int tid  = threadIdx.x;
    const int lane = tid & 31;
    const int w    = tid >> 5;
    const int g4w  = w & 3;
    const int role = w >> 2;
    const int bi   = blockIdx.x >> 4;   // row group == cluster index
    const int bu   = blockIdx.x & 15;
    const int r0   = bi * 32;
    const int u0   = bu * 16;

    // ---- prologue: weights -> bf16-pair SMEM planes ----
    #pragma unroll 4
    for (int it = 0; it < 16; ++it) {
        int idx = tid + it * THREADS_R;
        int cc  = idx >> 6;
        int kf  = idx & 63;
        int g4  = cc >> 4, uu = cc & 15;
        float4 v = *(const float4*)(&Whh[(size_t)(g4 * HID + u0 + uu) * HID + kf * 4]);
        uint2 hi, lo; cvt_pair4(v, hi, lo);
        *(uint2*)(smr + R_WH_HI + cc * RPITCH + kf * 8) = hi;
        *(uint2*)(smr + R_WH_LO + cc * RPITCH + kf * 8) = lo;
    }
    if (FUSED) {
        #pragma unroll 4
        for (int it = 0; it < 16; ++it) {
            int idx = tid + it * THREADS_R;
            int cc  = idx >> 6;
            int kf  = idx & 63;
            int g4  = cc >> 4, uu = cc & 15;
            float4 v = *(const float4*)(&Wih_next[(size_t)(g4 * HID + u0 + uu) * HID + kf * 4]);
            uint2 hi, lo; cvt_pair4(v, hi, lo);
            *(uint2*)(smr + R_WN_HI + cc * RPITCH + kf * 8) = hi;
            *(uint2*)(smr + R_WN_LO + cc * RPITCH + kf * 8) = lo;
        }
        if (tid < 64) {
            int g4 = tid >> 4, uu = tid & 15;
            sbn[tid] = bn1[g4 * HID + u0 + uu] + bn2[g4 * HID + u0 + uu];
        }
    }
    for (int q = tid; q < 512; q += THREADS_R) {
        int r = q & 31, uu = q >> 5;
        g_hbf[0][0][(r0 + r) * HID + u0 + uu] = __float2bfloat16(0.0f);
        g_hbf[0][1][(r0 + r) * HID + u0 + uu] = __float2bfloat16(0.0f);
    }
    for (int q = tid; q < 32 * 17; q += THREADS_R) Cs[q] = 0.0f;
    // initial visibility of zeroed h across the group
    if (CLUSTERED) __threadfence();
    step_sync<CLUSTERED>(bi);

    const int gq  = lane >> 2;
    const int tig = lane & 3;
    const int row_a = lane;

    const float* xp_base = xpre_in + ((size_t)(r0 + row_a) * SEQ) * G4H + u0 + w * 2;

    float xv[4][2];
    #pragma unroll
    for (int g4 = 0; g4 < 4; ++g4) {
        float2 f = *(const float2*)(xp_base + (size_t)g4 * HID);
        xv[g4][0] = f.x; xv[g4][1] = f.y;
    }

    int cur = 0;
    for (int t = 0; t < SEQ; ++t) {
        load_h_tile(smr, g_hbf[cur][0], g_hbf[cur][1], r0, tid);
        __syncthreads();

        if (FUSED) {
            if (role == 0) {
                float acc[2][2][4] = {};
                pair_mma(sbase, lane, g4w, 0, 16, R_WH_HI, R_WH_LO, acc);
                #pragma unroll
                for (int mi = 0; mi < 2; ++mi)
                    #pragma unroll
                    for (int ni = 0; ni < 2; ++ni) {
                        const int col = g4w * 16 + ni * 8 + tig * 2;
                        *(float2*)(&Gs0[(mi * 16 + gq) * 66 + col])     = make_float2(acc[mi][ni][0], acc[mi][ni][1]);
                        *(float2*)(&Gs0[(mi * 16 + gq + 8) * 66 + col]) = make_float2(acc[mi][ni][2], acc[mi][ni][3]);
                    }
            } else {
                float acc2[2][2][4] = {};
                pair_mma(sbase, lane, g4w, 0, 16, R_WN_HI, R_WN_LO, acc2);
                if (t > 0)
                    proj_store(xpre_out, sbn, acc2, t - 1, r0, u0, g4w, gq, tig);
            }
        } else {
            float acc[2][2][4] = {};
            pair_mma(sbase, lane, g4w, role * 8, role * 8 + 8, R_WH_HI, R_WH_LO, acc);
            float* Gp = role == 0 ? Gs0 : Gs1;
            #pragma unroll
            for (int mi = 0; mi < 2; ++mi)
                #pragma unroll
                for (int ni = 0; ni < 2; ++ni) {
                    const int col = g4w * 16 + ni * 8 + tig * 2;
                    *(float2*)(&Gp[(mi * 16 + gq) * 66 + col])     = make_float2(acc[mi][ni][0], acc[mi][ni][1]);
                    *(float2*)(&Gp[(mi * 16 + gq + 8) * 66 + col]) = make_float2(acc[mi][ni][2], acc[mi][ni][3]);
                }
        }
        __syncthreads();

        // ---- activations: thread owns (row_a, units w*2..+1) ----
        __nv_bfloat16* dhi = g_hbf[cur ^ 1][0];
        __nv_bfloat16* dlo = g_hbf[cur ^ 1][1];
        unsigned hh[2], hl[2];
        float2 yv, cv;
        float* ys  = (float*)&yv;
        float* cs2 = (float*)&cv;
        #pragma unroll
        for (int j = 0; j < 2; ++j) {
            int uu = w * 2 + j;
            float gi, gf, gg, go;
            if (FUSED) {
                gi = Gs0[row_a * 66 +      uu];
                gf = Gs0[row_a * 66 + 16 + uu];
                gg = Gs0[row_a * 66 + 32 + uu];
                go = Gs0[row_a * 66 + 48 + uu];
            } else {
                gi = Gs0[row_a * 66 +      uu] + Gs1[row_a * 66 +      uu];
                gf = Gs0[row_a * 66 + 16 + uu] + Gs1[row_a * 66 + 16 + uu];
                gg = Gs0[row_a * 66 + 32 + uu] + Gs1[row_a * 66 + 32 + uu];
                go = Gs0[row_a * 66 + 48 + uu] + Gs1[row_a * 66 + 48 + uu];
            }
            gi += xv[0][j]; gf += xv[1][j]; gg += xv[2][j]; go += xv[3][j];
            float ig = sigmoidf_(gi);
            float fg = sigmoidf_(gf);
            float og = sigmoidf_(go);
            float gc = tanhf(gg);
            float c  = fg * Cs[row_a * 17 + uu] + ig * gc;
            float h  = og * tanhf(c);
            Cs[row_a * 17 + uu] = c;
            __nv_bfloat16 hb = __float2bfloat16(h);
            float hf = __bfloat162float(hb);
            __nv_bfloat16 lb = __float2bfloat16(h - hf);
            hh[j] = (unsigned)__bfloat16_as_ushort(hb);
            hl[j] = (unsigned)__bfloat16_as_ushort(lb);
            ys[j] = h;
            cs2[j] = c;
        }
        {
            const int uoff = (r0 + row_a) * HID + u0 + w * 2;
            *(unsigned*)(dhi + uoff) = hh[0] | (hh[1] << 16);
            *(unsigned*)(dlo + uoff) = hl[0] | (hl[1] << 16);
            if (y_out != nullptr)
                *(float2*)(&y_out[((size_t)(r0 + row_a) * SEQ + t) * HID + u0 + w * 2]) = yv;
            if (out_h != nullptr && t == SEQ - 1) {
                *(float2*)(&out_h[uoff]) = yv;
                *(float2*)(&out_c[uoff]) = cv;
            }
        }

        if (t + 1 < SEQ) {
            const float* xp = xp_base + (size_t)(t + 1) * G4H;
            #pragma unroll
            for (int g4 = 0; g4 < 4; ++g4) {
                float2 f = *(const float2*)(xp + (size_t)g4 * HID);
                xv[g4][0] = f.x; xv[g4][1] = f.y;
            }
        }

        step_sync<CLUSTERED>(bi);
        cur ^= 1;
    }

    // ---- epilogue (FUSED): project h_{SEQ-1} -> xpre_out[:, SEQ-1] ----
    if (FUSED) {
        load_h_tile(smr, g_hbf[cur][0], g_hbf[cur][1], r0, tid);
        __syncthreads();
        if (role == 1) {
            float acc2[2][2][4] = {};
            pair_mma(sbase, lane, g4w, 0, 16, R_WN_HI, R_WN_LO, acc2);
            proj_store(xpre_out, sbn, acc2, SEQ - 1, r0, u0, g4w, gq, tig);
        }
    }
}

// ================= launch =================
extern "C" void kernel_launch(void* const* d_in, const int* in_sizes, int n_in,
                              void* d_out, int out_size)
{
    const float* x    = (const float*)d_in[0];
    const float* Wih0 = (const float*)d_in[1];
    const float* Whh0 = (const float*)d_in[2];
    const float* bih0 = (const float*)d_in[3];
    const float* bhh0 = (const float*)d_in[4];
    const float* Wih1 = (const float*)d_in[5];
    const float* Whh1 = (const float*)d_in[6];
    const float* bih1 = (const float*)d_in[7];
    const float* bhh1 = (const float*)d_in[8];
    float* out = (float*)d_out;

    float* xpre0 = nullptr;
    float* xpre1 = nullptr;
    cudaGetSymbolAddress((void**)&xpre0, g_xpre0);
    cudaGetSymbolAddress((void**)&xpre1, g_xpre1);

    cudaFuncSetAttribute(gemm_mma<INP>,
                         cudaFuncAttributeMaxDynamicSharedMemorySize, (int)GM_SMEM);
    cudaFuncSetAttribute(lstm_layer_kernel<true, false>,
                         cudaFuncAttributeMaxDynamicSharedMemorySize, (int)R_SMEM);
    cudaFuncSetAttribute(lstm_layer_kernel<false, false>,
                         cudaFuncAttributeMaxDynamicSharedMemorySize, (int)R_SMEM);
    cudaFuncSetAttribute(lstm_layer_kernel<true, true>,
                         cudaFuncAttributeMaxDynamicSharedMemorySize, (int)R_SMEM);
    cudaFuncSetAttribute(lstm_layer_kernel<false, true>,
                         cudaFuncAttributeMaxDynamicSharedMemorySize, (int)R_SMEM);
    cudaFuncSetAttribute(lstm_layer_kernel<true, true>,
                         cudaFuncAttributeNonPortableClusterSizeAllowed, 1);
    cudaFuncSetAttribute(lstm_layer_kernel<false, true>,
                         cudaFuncAttributeNonPortableClusterSizeAllowed, 1);

    // Deterministic capability probe: can a 16-CTA cluster launch with our config?
    bool cluster_ok = false;
    {
        cudaLaunchConfig_t probe = {};
        probe.gridDim = dim3(GRID_P, 1, 1);
        probe.blockDim = dim3(THREADS_R, 1, 1);
        probe.dynamicSmemBytes = R_SMEM;
        int mc0 = 0, mc1 = 0;
        cudaOccupancyMaxPotentialClusterSize(&mc0, lstm_layer_kernel<true, true>, &probe);
        cudaOccupancyMaxPotentialClusterSize(&mc1, lstm_layer_kernel<false, true>, &probe);
        cluster_ok = (mc0 >= GROUP_CTAS) && (mc1 >= GROUP_CTAS);
        cudaGetLastError();   // clear any probe error
    }

    dim3 tgrid(G4H / 128, (BATCH * SEQ) / 128);   // (8, 1024)
    float* out_h = out + (size_t)BATCH * SEQ * HID;
    float* out_c = out_h + (size_t)BATCH * HID;

    // Layer 0: input projection first
    gemm_mma<INP><<<tgrid, GM_THREADS, GM_SMEM>>>(x, Wih0, bih0, bhh0, xpre0);

    if (cluster_ok) {
        cudaLaunchConfig_t cfg = {};
        cfg.gridDim = dim3(GRID_P, 1, 1);
        cfg.blockDim = dim3(THREADS_R, 1, 1);
        cfg.dynamicSmemBytes = R_SMEM;
        cudaLaunchAttribute attrs[1];
        attrs[0].id = cudaLaunchAttributeClusterDimension;
        attrs[0].val.clusterDim = {GROUP_CTAS, 1, 1};
        cfg.attrs = attrs;
        cfg.numAttrs = 1;

        float* np = nullptr;
        cudaLaunchKernelEx(&cfg, lstm_layer_kernel<true, true>,
                           Whh0, (const float*)xpre0, Wih1, bih1, bhh1,
                           xpre1, np, np, np);
        cudaLaunchKernelEx(&cfg, lstm_layer_kernel<false, true>,
                           Whh1, (const float*)xpre1, (const float*)nullptr,
                           (const float*)nullptr, (const float*)nullptr,
                           (float*)nullptr, out, out_h, out_c);
    } else {
        lstm_layer_kernel<true, false><<<GRID_P, THREADS_R, R_SMEM>>>(
            Whh0, xpre0, Wih1, bih1, bhh1, xpre1, nullptr, nullptr, nullptr);
        lstm_layer_kernel<false, false><<<GRID_P, THREADS_R, R_SMEM>>>(
            Whh1, xpre1, nullptr, nullptr, nullptr, nullptr, out, out_h, out_c);
    }
}

// round 16
// speedup vs baseline: 1.7250x; 1.7250x over previous
#include <cuda_runtime.h>
#include <cuda_bf16.h>
#include <cstdint>
#include <cstddef>

// Problem constants
constexpr int BATCH = 256;
constexpr int SEQ   = 512;
constexpr int INP   = 128;
constexpr int HID   = 256;
constexpr int G4H   = 1024;   // 4*HID

// Persistent recurrent kernel config
constexpr int GRID_P    = 128;   // 8 row-blocks x 16 unit-blocks
constexpr int THREADS_R = 256;   // 8 warps
constexpr int GROUP_CTAS = 16;   // CTAs per row-block sync group

// ---------------- scratch ----------------
__device__ float g_xpre0[(size_t)BATCH * SEQ * G4H];       // 512 MB
__device__ float g_xpre1[(size_t)BATCH * SEQ * G4H];       // 512 MB
__device__ __nv_bfloat16 g_hbf[2][2][BATCH * HID];         // [buf][hi/lo][B*H]
__device__ unsigned int g_grp_count[8][64];
__device__ unsigned int g_grp_gen[8][64];
// produce/consume flags: [layer][group][producer][pad 128B]
__device__ int g_flags0[8][GROUP_CTAS][32];
__device__ int g_flags1[8][GROUP_CTAS][32];

__device__ __forceinline__ uint32_t smem_u32(const void* p) {
    uint32_t a;
    asm("{ .reg .u64 t; cvta.to.shared.u64 t, %1; cvt.u32.u64 %0, t; }" : "=r"(a) : "l"(p));
    return a;
}

// ================= mma.sync helpers =================
__device__ __forceinline__ void ldmx4(uint32_t* r, uint32_t addr) {
    asm volatile("ldmatrix.sync.aligned.m8n8.x4.shared.b16 {%0,%1,%2,%3}, [%4];"
                 : "=r"(r[0]), "=r"(r[1]), "=r"(r[2]), "=r"(r[3]) : "r"(addr));
}
__device__ __forceinline__ void mma16816(float* d, const uint32_t* a,
                                         uint32_t b0, uint32_t b1) {
    asm volatile(
        "mma.sync.aligned.m16n8k16.row.col.f32.bf16.bf16.f32 "
        "{%0,%1,%2,%3}, {%4,%5,%6,%7}, {%8,%9}, {%0,%1,%2,%3};"
        : "+f"(d[0]), "+f"(d[1]), "+f"(d[2]), "+f"(d[3])
        : "r"(a[0]), "r"(a[1]), "r"(a[2]), "r"(a[3]), "r"(b0), "r"(b1));
}

__device__ __forceinline__ void cvt_pair8(const float* v, uint4& hi, uint4& lo) {
    unsigned hs[8], ls[8];
    #pragma unroll
    for (int j = 0; j < 8; ++j) {
        __nv_bfloat16 h = __float2bfloat16(v[j]);
        float hf = __bfloat162float(h);
        __nv_bfloat16 l = __float2bfloat16(v[j] - hf);
        hs[j] = (unsigned)__bfloat16_as_ushort(h);
        ls[j] = (unsigned)__bfloat16_as_ushort(l);
    }
    hi.x = hs[0] | (hs[1] << 16); hi.y = hs[2] | (hs[3] << 16);
    hi.z = hs[4] | (hs[5] << 16); hi.w = hs[6] | (hs[7] << 16);
    lo.x = ls[0] | (ls[1] << 16); lo.y = ls[2] | (ls[3] << 16);
    lo.z = ls[4] | (ls[5] << 16); lo.w = ls[6] | (ls[7] << 16);
}
__device__ __forceinline__ void cvt_pair4(float4 v, uint2& hi, uint2& lo) {
    float f[4] = {v.x, v.y, v.z, v.w};
    unsigned hs[4], ls[4];
    #pragma unroll
    for (int j = 0; j < 4; ++j) {
        __nv_bfloat16 h = __float2bfloat16(f[j]);
        float hf = __bfloat162float(h);
        __nv_bfloat16 l = __float2bfloat16(f[j] - hf);
        hs[j] = (unsigned)__bfloat16_as_ushort(h);
        ls[j] = (unsigned)__bfloat16_as_ushort(l);
    }
    hi.x = hs[0] | (hs[1] << 16); hi.y = hs[2] | (hs[3] << 16);
    lo.x = ls[0] | (ls[1] << 16); lo.y = ls[2] | (ls[3] << 16);
}

// ================= input-projection GEMM on HMMA (layer 0, validated) =================
constexpr int GM_THREADS = 256;
constexpr int PITCH = 80;
constexpr int PLANE = 128 * PITCH;
constexpr int SB_BIAS = 0;
constexpr int SB_AH = 1024;
constexpr int SB_AL = SB_AH + PLANE;
constexpr int SB_BH = SB_AL + PLANE;
constexpr int SB_BL = SB_BH + PLANE;
constexpr size_t GM_SMEM = SB_BL + PLANE;

template<int K>
__global__ void __launch_bounds__(GM_THREADS)
gemm_mma(const float* __restrict__ A, const float* __restrict__ W,
         const float* __restrict__ b1, const float* __restrict__ b2,
         float* __restrict__ Cout)
{
    extern __shared__ char sm[];
    const uint32_t sbase = smem_u32(sm);
    float* sbias = (float*)(sm + SB_BIAS);

    const int tid  = threadIdx.x;
    const int lane = tid & 31;
    const int warp = tid >> 5;
    const int wm   = warp >> 2;
    const int wn   = warp & 3;
    const int n0   = blockIdx.x * 128;
    const size_t m0 = (size_t)blockIdx.y * 128;

    if (tid < 128) sbias[tid] = b1[n0 + tid] + b2[n0 + tid];

    const int lrow  = tid >> 1;
    const int lhalf = tid & 1;
    const float* gA = A + (m0 + lrow) * K + lhalf * 16;
    const float* gB = W + (size_t)(n0 + lrow) * K + lhalf * 16;

    float acc[4][4][4] = {};
    float ra[16], rb[16];

    #pragma unroll
    for (int q = 0; q < 4; ++q) {
        *(float4*)(ra + q * 4) = *(const float4*)(gA + q * 4);
        *(float4*)(rb + q * 4) = *(const float4*)(gB + q * 4);
    }

    constexpr int NC = K / 32;
    for (int c = 0; c < NC; ++c) {
        #pragma unroll
        for (int j = 0; j < 2; ++j) {
            uint4 hi, lo;
            uint32_t off = (uint32_t)(lrow * PITCH + lhalf * 32 + j * 16);
            cvt_pair8(ra + j * 8, hi, lo);
            *(uint4*)(sm + SB_AH + off) = hi;
            *(uint4*)(sm + SB_AL + off) = lo;
            cvt_pair8(rb + j * 8, hi, lo);
            *(uint4*)(sm + SB_BH + off) = hi;
            *(uint4*)(sm + SB_BL + off) = lo;
        }
        __syncthreads();

        if (c + 1 < NC) {
            #pragma unroll
            for (int q = 0; q < 4; ++q) {
                *(float4*)(ra + q * 4) = *(const float4*)(gA + (c + 1) * 32 + q * 4);
                *(float4*)(rb + q * 4) = *(const float4*)(gB + (c + 1) * 32 + q * 4);
            }
        }

        #pragma unroll
        for (int kb = 0; kb < 2; ++kb) {
            uint32_t Ah[4][4], Al[4][4], Bh[2][4], Bl[2][4];
            const uint32_t acol = (uint32_t)(kb * 32 + (lane >> 4) * 16);
            #pragma unroll
            for (int mi = 0; mi < 4; ++mi) {
                uint32_t rowoff = (uint32_t)((wm * 64 + mi * 16 + (lane & 15)) * PITCH) + acol;
                ldmx4(Ah[mi], sbase + SB_AH + rowoff);
                ldmx4(Al[mi], sbase + SB_AL + rowoff);
            }
            const uint32_t bcol = (uint32_t)(kb * 32 + ((lane >> 3) & 1) * 16);
            #pragma unroll
            for (int nb = 0; nb < 2; ++nb) {
                uint32_t rowoff = (uint32_t)((wn * 32 + nb * 16 + (lane & 7) + ((lane >> 4) << 3)) * PITCH) + bcol;
                ldmx4(Bh[nb], sbase + SB_BH + rowoff);
                ldmx4(Bl[nb], sbase + SB_BL + rowoff);
            }
            #pragma unroll
            for (int mi = 0; mi < 4; ++mi) {
                #pragma unroll
                for (int ni = 0; ni < 4; ++ni) {
                    const int nb = ni >> 1, h = (ni & 1) * 2;
                    mma16816(acc[mi][ni], Ah[mi], Bh[nb][h], Bh[nb][h + 1]);
                    mma16816(acc[mi][ni], Ah[mi], Bl[nb][h], Bl[nb][h + 1]);
                    mma16816(acc[mi][ni], Al[mi], Bh[nb][h], Bh[nb][h + 1]);
                }
            }
        }
        __syncthreads();
    }

    const int g   = lane >> 2;
    const int tig = lane & 3;
    #pragma unroll
    for (int mi = 0; mi < 4; ++mi) {
        const size_t row = m0 + wm * 64 + mi * 16 + g;
        float* dst0 = Cout + row * G4H + n0;
        float* dst8 = dst0 + (size_t)8 * G4H;
        #pragma unroll
        for (int ni = 0; ni < 4; ++ni) {
            const int col = wn * 32 + ni * 8 + tig * 2;
            const float bb0 = sbias[col], bb1 = sbias[col + 1];
            float2 v0 = {acc[mi][ni][0] + bb0, acc[mi][ni][1] + bb1};
            float2 v1 = {acc[mi][ni][2] + bb0, acc[mi][ni][3] + bb1};
            *(float2*)(dst0 + col) = v0;
            *(float2*)(dst8 + col) = v1;
        }
    }
}

// ================= barriers / flags =================
__device__ __forceinline__ void group_sync_atomic(int grp)
{
    __syncthreads();
    if (threadIdx.x == 0) {
        __threadfence();
        unsigned int gen  = *((volatile unsigned int*)&g_grp_gen[grp][0]);
        unsigned int prev = atomicAdd(&g_grp_count[grp][0], 1u);
        if (prev == GROUP_CTAS - 1) {
            g_grp_count[grp][0] = 0;
            __threadfence();
            atomicAdd(&g_grp_gen[grp][0], 1u);
        } else {
            while (*((volatile unsigned int*)&g_grp_gen[grp][0]) == gen) { }
            __threadfence();
        }
    }
    __syncthreads();
}

// Wait until all 16 producers in this group have published version >= t.
// Threads 0..15 poll distinct flags in parallel (no atomic serialization).
__device__ __forceinline__ void flags_wait(int* flags, int bi, int t)
{
    if (threadIdx.x < GROUP_CTAS) {
        const volatile int* f = (const volatile int*)&flags[(bi * GROUP_CTAS + threadIdx.x) * 32];
        while (*f < t) { }
        __threadfence();
    }
    __syncthreads();
}

__device__ __forceinline__ float sigmoidf_(float x) { return 1.0f / (1.0f + __expf(-x)); }

// ================= persistent LSTM recurrence, warp-specialized ========
constexpr int RPITCH  = 528;
constexpr int R_WH_HI = 0;
constexpr int R_WH_LO = R_WH_HI + 64 * RPITCH;
constexpr int R_WN_HI = R_WH_LO + 64 * RPITCH;
constexpr int R_WN_LO = R_WN_HI + 64 * RPITCH;
constexpr int R_AH    = R_WN_LO + 64 * RPITCH;
constexpr int R_AL    = R_AH + 32 * RPITCH;
constexpr int R_GS    = R_AL + 32 * RPITCH;
constexpr int GS_PLANE = 32 * 66;
constexpr int R_CS    = R_GS + 2 * GS_PLANE * 4;
constexpr int R_BN    = R_CS + 32 * 17 * 4;
constexpr size_t R_SMEM = (size_t)R_BN + 64 * 4;    // 188288 B

__device__ __forceinline__ void load_h_tile(char* smr, const __nv_bfloat16* hhi,
                                            const __nv_bfloat16* hlo, int r0, int tid)
{
    #pragma unroll
    for (int it = 0; it < 4; ++it) {
        int idx = tid + it * THREADS_R;
        int row = idx >> 5, ch = idx & 31;
        uint4 v = __ldcg((const uint4*)(hhi + (r0 + row) * HID) + ch);
        *(uint4*)(smr + R_AH + row * RPITCH + ch * 16) = v;
        v = __ldcg((const uint4*)(hlo + (r0 + row) * HID) + ch);
        *(uint4*)(smr + R_AL + row * RPITCH + ch * 16) = v;
    }
}

__device__ __forceinline__ void pair_mma(const uint32_t sbase, int lane, int g4,
                                         int kb0, int kb1, int whi, int wlo,
                                         float acc[2][2][4])
{
    for (int kb = kb0; kb < kb1; ++kb) {
        uint32_t Ahf[2][4], Alf[2][4], Bhf[4], Blf[4];
        const uint32_t acol = (uint32_t)(kb * 32 + (lane >> 4) * 16);
        #pragma unroll
        for (int mi = 0; mi < 2; ++mi) {
            uint32_t ro = (uint32_t)((mi * 16 + (lane & 15)) * RPITCH) + acol;
            ldmx4(Ahf[mi], sbase + R_AH + ro);
            ldmx4(Alf[mi], sbase + R_AL + ro);
        }
        const uint32_t brow = (uint32_t)(g4 * 16 + (lane & 7) + ((lane >> 4) << 3));
        const uint32_t bcol = (uint32_t)(kb * 32 + ((lane >> 3) & 1) * 16);
        ldmx4(Bhf, sbase + whi + brow * RPITCH + bcol);
        ldmx4(Blf, sbase + wlo + brow * RPITCH + bcol);
        #pragma unroll
        for (int mi = 0; mi < 2; ++mi)
            #pragma unroll
            for (int ni = 0; ni < 2; ++ni) {
                const int h2 = ni * 2;
                mma16816(acc[mi][ni], Ahf[mi], Bhf[h2], Bhf[h2 + 1]);
                mma16816(acc[mi][ni], Ahf[mi], Blf[h2], Blf[h2 + 1]);
                mma16816(acc[mi][ni], Alf[mi], Bhf[h2], Bhf[h2 + 1]);
            }
    }
}

__device__ __forceinline__ void proj_store(float* __restrict__ xpre_out, const float* sbn,
                                           float acc2[2][2][4], int t_store,
                                           int r0, int u0, int g4, int gq, int tig)
{
    #pragma unroll
    for (int mi = 0; mi < 2; ++mi) {
        const int row = r0 + mi * 16 + gq;
        float* d0 = xpre_out + ((size_t)row * SEQ + t_store) * G4H + g4 * HID + u0;
        float* d8 = xpre_out + ((size_t)(row + 8) * SEQ + t_store) * G4H + g4 * HID + u0;
        #pragma unroll
        for (int ni = 0; ni < 2; ++ni) {
            const int uu = ni * 8 + tig * 2;
            const float b0 = sbn[g4 * 16 + uu], b1v = sbn[g4 * 16 + uu + 1];
            float2 v0 = {acc2[mi][ni][0] + b0, acc2[mi][ni][1] + b1v};
            float2 v1 = {acc2[mi][ni][2] + b0, acc2[mi][ni][3] + b1v};
            *(float2*)(d0 + uu) = v0;
            *(float2*)(d8 + uu) = v1;
        }
    }
}

template<bool FUSED>
__global__ void __launch_bounds__(THREADS_R, 1)
lstm_layer_kernel(const float* __restrict__ Whh,
                  const float* __restrict__ xpre_in,
                  const float* __restrict__ Wih_next,
                  const float* __restrict__ bn1,
                  const float* __restrict__ bn2,
                  float* __restrict__ xpre_out,
                  float* __restrict__ y_out,
                  float* __restrict__ out_h,
                  float* __restrict__ out_c,
                  int* __restrict__ flags)
{
    extern __shared__ char smr[];
    const uint32_t sbase = smem_u32(smr);
    float* Gs0 = (float*)(smr + R_GS);
    float* Gs1 = Gs0 + GS_PLANE;
    float* Cs  = (float*)(smr + R_CS);
    float* sbn = (float*)(smr + R_BN);

    const int tid  = threadIdx.x;
    const int lane = tid & 31;
    const int w    = tid >> 5;
    const int g4w  = w & 3;
    const int role = w >> 2;
    const int bi   = blockIdx.x >> 4;
    const int bu   = blockIdx.x & 15;
    const int r0   = bi * 32;
    const int u0   = bu * 16;

    // ---- prologue: weights -> bf16-pair SMEM planes ----
    #pragma unroll 4
    for (int it = 0; it < 16; ++it) {
        int idx = tid + it * THREADS_R;
        int cc  = idx >> 6;
        int kf  = idx & 63;
        int g4  = cc >> 4, uu = cc & 15;
        float4 v = *(const float4*)(&Whh[(size_t)(g4 * HID + u0 + uu) * HID + kf * 4]);
        uint2 hi, lo; cvt_pair4(v, hi, lo);
        *(uint2*)(smr + R_WH_HI + cc * RPITCH + kf * 8) = hi;
        *(uint2*)(smr + R_WH_LO + cc * RPITCH + kf * 8) = lo;
    }
    if (FUSED) {
        #pragma unroll 4
        for (int it = 0; it < 16; ++it) {
            int idx = tid + it * THREADS_R;
            int cc  = idx >> 6;
            int kf  = idx & 63;
            int g4  = cc >> 4, uu = cc & 15;
            float4 v = *(const float4*)(&Wih_next[(size_t)(g4 * HID + u0 + uu) * HID + kf * 4]);
            uint2 hi, lo; cvt_pair4(v, hi, lo);
            *(uint2*)(smr + R_WN_HI + cc * RPITCH + kf * 8) = hi;
            *(uint2*)(smr + R_WN_LO + cc * RPITCH + kf * 8) = lo;
        }
        if (tid < 64) {
            int g4 = tid >> 4, uu = tid & 15;
            sbn[tid] = bn1[g4 * HID + u0 + uu] + bn2[g4 * HID + u0 + uu];
        }
    }
    for (int q = tid; q < 512; q += THREADS_R) {
        int r = q & 31, uu = q >> 5;
        g_hbf[0][0][(r0 + r) * HID + u0 + uu] = __float2bfloat16(0.0f);
        g_hbf[0][1][(r0 + r) * HID + u0 + uu] = __float2bfloat16(0.0f);
    }
    for (int q = tid; q < 32 * 17; q += THREADS_R) Cs[q] = 0.0f;
    group_sync_atomic(bi);   // init h visible; flags are 0 (reset by prior run's tail)

    const int gq  = lane >> 2;
    const int tig = lane & 3;
    const int row_a = lane;

    const float* xp_base = xpre_in + ((size_t)(r0 + row_a) * SEQ) * G4H + u0 + w * 2;

    float xv[4][2];
    #pragma unroll
    for (int g4 = 0; g4 < 4; ++g4) {
        float2 f = *(const float2*)(xp_base + (size_t)g4 * HID);
        xv[g4][0] = f.x; xv[g4][1] = f.y;
    }

    int cur = 0;
    for (int t = 0; t < SEQ; ++t) {
        // wait for all producers to have published h_{t-1} (version t)
        flags_wait(flags, bi, t);

        load_h_tile(smr, g_hbf[cur][0], g_hbf[cur][1], r0, tid);
        __syncthreads();

        if (FUSED) {
            if (role == 0) {
                float acc[2][2][4] = {};
                pair_mma(sbase, lane, g4w, 0, 16, R_WH_HI, R_WH_LO, acc);
                #pragma unroll
                for (int mi = 0; mi < 2; ++mi)
                    #pragma unroll
                    for (int ni = 0; ni < 2; ++ni) {
                        const int col = g4w * 16 + ni * 8 + tig * 2;
                        *(float2*)(&Gs0[(mi * 16 + gq) * 66 + col])     = make_float2(acc[mi][ni][0], acc[mi][ni][1]);
                        *(float2*)(&Gs0[(mi * 16 + gq + 8) * 66 + col]) = make_float2(acc[mi][ni][2], acc[mi][ni][3]);
                    }
            } else {
                float acc2[2][2][4] = {};
                pair_mma(sbase, lane, g4w, 0, 16, R_WN_HI, R_WN_LO, acc2);
                if (t > 0)
                    proj_store(xpre_out, sbn, acc2, t - 1, r0, u0, g4w, gq, tig);
            }
        } else {
            float acc[2][2][4] = {};
            pair_mma(sbase, lane, g4w, role * 8, role * 8 + 8, R_WH_HI, R_WH_LO, acc);
            float* Gp = role == 0 ? Gs0 : Gs1;
            #pragma unroll
            for (int mi = 0; mi < 2; ++mi)
                #pragma unroll
                for (int ni = 0; ni < 2; ++ni) {
                    const int col = g4w * 16 + ni * 8 + tig * 2;
                    *(float2*)(&Gp[(mi * 16 + gq) * 66 + col])     = make_float2(acc[mi][ni][0], acc[mi][ni][1]);
                    *(float2*)(&Gp[(mi * 16 + gq + 8) * 66 + col]) = make_float2(acc[mi][ni][2], acc[mi][ni][3]);
                }
        }
        __syncthreads();

        // ---- activations: thread owns (row_a, units w*2..+1) ----
        __nv_bfloat16* dhi = g_hbf[cur ^ 1][0];
        __nv_bfloat16* dlo = g_hbf[cur ^ 1][1];
        unsigned hh[2], hl[2];
        float2 yv, cv;
        float* ys  = (float*)&yv;
        float* cs2 = (float*)&cv;
        #pragma unroll
        for (int j = 0; j < 2; ++j) {
            int uu = w * 2 + j;
            float gi, gf, gg, go;
            if (FUSED) {
                gi = Gs0[row_a * 66 +      uu];
                gf = Gs0[row_a * 66 + 16 + uu];
                gg = Gs0[row_a * 66 + 32 + uu];
                go = Gs0[row_a * 66 + 48 + uu];
            } else {
                gi = Gs0[row_a * 66 +      uu] + Gs1[row_a * 66 +      uu];
                gf = Gs0[row_a * 66 + 16 + uu] + Gs1[row_a * 66 + 16 + uu];
                gg = Gs0[row_a * 66 + 32 + uu] + Gs1[row_a * 66 + 32 + uu];
                go = Gs0[row_a * 66 + 48 + uu] + Gs1[row_a * 66 + 48 + uu];
            }
            gi += xv[0][j]; gf += xv[1][j]; gg += xv[2][j]; go += xv[3][j];
            float ig = sigmoidf_(gi);
            float fg = sigmoidf_(gf);
            float og = sigmoidf_(go);
            float gc = tanhf(gg);
            float c  = fg * Cs[row_a * 17 + uu] + ig * gc;
            float h  = og * tanhf(c);
            Cs[row_a * 17 + uu] = c;
            __nv_bfloat16 hb = __float2bfloat16(h);
            float hf = __bfloat162float(hb);
            __nv_bfloat16 lb = __float2bfloat16(h - hf);
            hh[j] = (unsigned)__bfloat16_as_ushort(hb);
            hl[j] = (unsigned)__bfloat16_as_ushort(lb);
            ys[j] = h;
            cs2[j] = c;
        }
        {
            const int uoff = (r0 + row_a) * HID + u0 + w * 2;
            *(unsigned*)(dhi + uoff) = hh[0] | (hh[1] << 16);
            *(unsigned*)(dlo + uoff) = hl[0] | (hl[1] << 16);
            if (y_out != nullptr)
                *(float2*)(&y_out[((size_t)(r0 + row_a) * SEQ + t) * HID + u0 + w * 2]) = yv;
            if (out_h != nullptr && t == SEQ - 1) {
                *(float2*)(&out_h[uoff]) = yv;
                *(float2*)(&out_c[uoff]) = cv;
            }
        }

        // all h stores done -> publish version t+1
        __syncthreads();
        if (tid == 0) {
            __threadfence();
            *((volatile int*)&flags[(bi * GROUP_CTAS + bu) * 32]) = t + 1;
        }

        // prefetch next step's xpre (overlaps with other CTAs finishing)
        if (t + 1 < SEQ) {
            const float* xp = xp_base + (size_t)(t + 1) * G4H;
            #pragma unroll
            for (int g4 = 0; g4 < 4; ++g4) {
                float2 f = *(const float2*)(xp + (size_t)g4 * HID);
                xv[g4][0] = f.x; xv[g4][1] = f.y;
            }
        }

        cur ^= 1;
    }

    // ---- epilogue (FUSED): project h_{SEQ-1} -> xpre_out[:, SEQ-1] ----
    if (FUSED) {
        flags_wait(flags, bi, SEQ);
        load_h_tile(smr, g_hbf[cur][0], g_hbf[cur][1], r0, tid);
        __syncthreads();
        if (role == 1) {
            float acc2[2][2][4] = {};
            pair_mma(sbase, lane, g4w, 0, 16, R_WN_HI, R_WN_LO, acc2);
            proj_store(xpre_out, sbn, acc2, SEQ - 1, r0, u0, g4w, gq, tig);
        }
    }

    // ---- tail: reset flags for the next replay (after everyone is done) ----
    group_sync_atomic(bi);
    if (tid == 0)
        *((volatile int*)&flags[(bi * GROUP_CTAS + bu) * 32]) = 0;
}

// ================= launch =================
extern "C" void kernel_launch(void* const* d_in, const int* in_sizes, int n_in,
                              void* d_out, int out_size)
{
    const float* x    = (const float*)d_in[0];
    const float* Wih0 = (const float*)d_in[1];
    const float* Whh0 = (const float*)d_in[2];
    const float* bih0 = (const float*)d_in[3];
    const float* bhh0 = (const float*)d_in[4];
    const float* Wih1 = (const float*)d_in[5];
    const float* Whh1 = (const float*)d_in[6];
    const float* bih1 = (const float*)d_in[7];
    const float* bhh1 = (const float*)d_in[8];
    float* out = (float*)d_out;

    float* xpre0 = nullptr;
    float* xpre1 = nullptr;
    int* flags0 = nullptr;
    int* flags1 = nullptr;
    cudaGetSymbolAddress((void**)&xpre0, g_xpre0);
    cudaGetSymbolAddress((void**)&xpre1, g_xpre1);
    cudaGetSymbolAddress((void**)&flags0, g_flags0);
    cudaGetSymbolAddress((void**)&flags1, g_flags1);

    cudaFuncSetAttribute(gemm_mma<INP>,
                         cudaFuncAttributeMaxDynamicSharedMemorySize, (int)GM_SMEM);
    cudaFuncSetAttribute(lstm_layer_kernel<true>,
                         cudaFuncAttributeMaxDynamicSharedMemorySize, (int)R_SMEM);
    cudaFuncSetAttribute(lstm_layer_kernel<false>,
                         cudaFuncAttributeMaxDynamicSharedMemorySize, (int)R_SMEM);

    dim3 tgrid(G4H / 128, (BATCH * SEQ) / 128);   // (8, 1024)
    float* out_h = out + (size_t)BATCH * SEQ * HID;
    float* out_c = out_h + (size_t)BATCH * HID;

    // Layer 0: input projection, then recurrence with warp-specialized fused layer-1 projection
    gemm_mma<INP><<<tgrid, GM_THREADS, GM_SMEM>>>(x, Wih0, bih0, bhh0, xpre0);
    lstm_layer_kernel<true><<<GRID_P, THREADS_R, R_SMEM>>>(
        Whh0, xpre0, Wih1, bih1, bhh1, xpre1, nullptr, nullptr, nullptr, flags0);

    // Layer 1: recurrence only, split-K across the 8 warps
    lstm_layer_kernel<false><<<GRID_P, THREADS_R, R_SMEM>>>(
        Whh1, xpre1, nullptr, nullptr, nullptr, nullptr, out, out_h, out_c, flags1);
}